// round 1
// baseline (speedup 1.0000x reference)
#include <cuda_runtime.h>
#include <cuda_bf16.h>

// Problem constants
#define BB 64
#define SS 784
#define TT 500
#define NN 512
#define KS 21
#define TP 522          // 500 + 2*21 - 21 + 1
#define THETA 40
#define NTILE 32        // neurons per tile
#define NTILES 16       // 512/32
#define NWARPS 16       // 512 threads

// Scratch (device globals; no runtime allocation allowed)
__device__ unsigned short g_spk[BB][TT][SS];   // spike lists (s indices)
__device__ int            g_cnt[BB][TT];       // list lengths
__device__ int            g_best[BB][TP][NTILES]; // per-tile argmax keys

// ---------------------------------------------------------------------------
// K0: zero output + spike counters
__global__ void k_zero(float4* __restrict__ out4, int n4) {
    int i = blockIdx.x * blockDim.x + threadIdx.x;
    int stride = gridDim.x * blockDim.x;
    float4 z = make_float4(0.f, 0.f, 0.f, 0.f);
    for (int j = i; j < n4; j += stride) out4[j] = z;
    int* cnt = &g_cnt[0][0];
    for (int j = i; j < BB * TT; j += stride) cnt[j] = 0;
}

// ---------------------------------------------------------------------------
// K1: build per-(b,t) active-synapse lists.  grid (SS, BB), 512 threads over t.
__global__ void k_spikes(const float* __restrict__ x) {
    int s = blockIdx.x, b = blockIdx.y;
    int t = threadIdx.x;
    if (t < TT) {
        float v = x[((size_t)b * SS + s) * TT + t];
        if (v > 0.5f) {
            int p = atomicAdd(&g_cnt[b][t], 1);
            g_spk[b][t][p] = (unsigned short)s;
        }
    }
}

// ---------------------------------------------------------------------------
// K2: potentials + per-tile argmax.  grid = BB*NTILES, block = 512.
// smem: sw[784*32] byte (=4*weight), scnt[500*32] u64 (byte-packed counts),
//       cE/cO[21] dp4a coefficient words.
#define SW_BYTES   (SS * NTILE)              // 25088
#define SCNT_BYTES (TT * NTILE * 8)          // 128000
#define SMEM_BYTES (SW_BYTES + SCNT_BYTES + 2 * KS * 4)

__global__ __launch_bounds__(512) void k_pot(const int* __restrict__ weight,
                                             const int* __restrict__ table) {
    extern __shared__ unsigned char smem[];
    unsigned char* sw = smem;
    unsigned long long* scnt = (unsigned long long*)(smem + SW_BYTES);
    unsigned int* cE = (unsigned int*)(smem + SW_BYTES + SCNT_BYTES);
    unsigned int* cO = cE + KS;

    int b = blockIdx.x >> 4, tile = blockIdx.x & 15;
    int tid = threadIdx.x, lane = tid & 31, warp = tid >> 5;

    // coefficient tables: orig[w][d] = table[w][20-d]; pack even/odd w into bytes
    if (tid < KS) {
        unsigned e = 0, o = 0;
#pragma unroll
        for (int w = 0; w < 4; w++) {
            e |= (unsigned)table[(2 * w) * KS + (KS - 1 - tid)] << (8 * w);
            o |= (unsigned)table[(2 * w + 1) * KS + (KS - 1 - tid)] << (8 * w);
        }
        cE[tid] = e; cO[tid] = o;
    }
    // weights -> smem as shift amounts (4*w), layout [s][n]
    for (int idx = tid; idx < NTILE * SS; idx += 512) {
        int n = idx / SS, s = idx - n * SS;           // consecutive tid -> consecutive s
        sw[s * NTILE + n] = (unsigned char)(weight[(size_t)(tile * NTILE + n) * SS + s] << 2);
    }
    __syncthreads();

    // ---- Phase A: per-timestep weight histograms (byte-packed counts) ----
    for (int t = warp; t < TT; t += NWARPS) {
        int cnt = g_cnt[b][t];
        const unsigned short* lst = g_spk[b][t];
        unsigned accE = 0, accO = 0;
        for (int j0 = 0; j0 < cnt; j0 += 32) {
            int m = min(32, cnt - j0);
            int sv = (j0 + lane < cnt) ? (int)lst[j0 + lane] : 0;
            unsigned nib = 0;
            for (int k = 0; k < m; k++) {
                int s = __shfl_sync(0xffffffffu, sv, k);
                nib += 1u << sw[s * NTILE + lane];
                if ((k & 7) == 7) {               // flush: nibbles can hold <=8 safely
                    accE += nib & 0x0F0F0F0Fu;
                    accO += (nib >> 4) & 0x0F0F0F0Fu;
                    nib = 0;
                }
            }
            accE += nib & 0x0F0F0F0Fu;
            accO += (nib >> 4) & 0x0F0F0F0Fu;
        }
        scnt[t * NTILE + lane] = (unsigned long long)accE | ((unsigned long long)accO << 32);
    }
    __syncthreads();

    // ---- Phase B: 147-tap exact conv via dp4a + per-tile warp argmax ----
    for (int c = warp; c < 25; c += NWARPS) {
        int c0 = c * KS;
        unsigned WE[KS], WO[KS];
#pragma unroll
        for (int i = 0; i < KS; i++) {
            int t = c0 - KS + i;
            unsigned long long v = (t >= 0 && t < TT) ? scnt[t * NTILE + lane] : 0ull;
            WE[i] = (unsigned)v; WO[i] = (unsigned)(v >> 32);
        }
#pragma unroll
        for (int j = 0; j < KS; j++) {
            int tau = c0 + j;
            if (tau < TP) {
                unsigned pot = 0;
#pragma unroll
                for (int d = 0; d < KS; d++) {
                    int sl = (j + 20 - d) % KS;   // slot holding t = tau-1-d
                    pot = __dp4a(WE[sl], cE[d], pot);
                    pot = __dp4a(WO[sl], cO[d], pot);
                }
                int key = ((int)pot << 8) | (255 - lane);   // ties -> smaller lane
#pragma unroll
                for (int off = 16; off; off >>= 1)
                    key = max(key, __shfl_xor_sync(0xffffffffu, key, off));
                if (lane == 0) g_best[b][tau][tile] = key;
            }
            // slide window: slot j takes t = c0 + j
            {
                int t2 = c0 + j;
                unsigned long long v = (t2 < TT) ? scnt[t2 * NTILE + lane] : 0ull;
                WE[j] = (unsigned)v; WO[j] = (unsigned)(v >> 32);
            }
        }
    }
}

// ---------------------------------------------------------------------------
// K3: reduce tiles + sequential depression scan. grid = BB, block = 256.
__global__ void k_scan(float* __restrict__ out) {
    int b = blockIdx.x, tid = threadIdx.x;
    __shared__ int mv[TP];
    __shared__ int mn[TP];
    for (int tau = tid; tau < TP; tau += blockDim.x) {
        int bestv = -1, bestn = 0;
#pragma unroll
        for (int tl = 0; tl < NTILES; tl++) {
            int k = g_best[b][tau][tl];
            int v = k >> 8;
            if (v > bestv) { bestv = v; bestn = tl * NTILE + (255 - (k & 255)); }
        }
        mv[tau] = bestv; mn[tau] = bestn;
    }
    __syncthreads();
    if (tid == 0) {
        int dep = 0;
        for (int tau = 0; tau < TP; tau++) {
            if (mv[tau] > THETA && dep == 0) {
                out[((size_t)b * NN + mn[tau]) * TP + tau] = 1.0f;
                dep = 22;       // becomes 21 after decrement, matching ref
            }
            dep = max(0, dep - 1);
        }
    }
}

// ---------------------------------------------------------------------------
extern "C" void kernel_launch(void* const* d_in, const int* in_sizes, int n_in,
                              void* d_out, int out_size) {
    const float* x      = (const float*)d_in[0];
    const int*   weight = (const int*)d_in[1];
    const int*   table  = (const int*)d_in[2];
    float* out = (float*)d_out;

    cudaFuncSetAttribute(k_pot, cudaFuncAttributeMaxDynamicSharedMemorySize, SMEM_BYTES);

    int n4 = out_size / 4;
    k_zero<<<2048, 256>>>((float4*)out, n4);
    k_spikes<<<dim3(SS, BB), 512>>>(x);
    k_pot<<<BB * NTILES, 512, SMEM_BYTES>>>(weight, table);
    k_scan<<<BB, 256>>>(out);
}

// round 2
// speedup vs baseline: 1.9344x; 1.9344x over previous
#include <cuda_runtime.h>
#include <cuda_bf16.h>

// Problem constants
#define BB 64
#define SS 784
#define TT 500
#define NN 512
#define KS 21
#define TP 522          // output time length
#define THETA 40
#define NTILE 32        // neurons per tile (one warp)
#define NTILES 16       // 512/32
#define NWARPS 16       // 512 threads

#define CH 87           // tau chunk (6 * 87 = 522)
#define SLOTS (CH + KS) // 108 count slots (21 halo)

// Scratch (device globals; no runtime allocation allowed)
__device__ unsigned short g_spk[BB][TT][SS];     // spike lists (s indices)
__device__ int            g_cnt[BB][TT];         // list lengths
__device__ int            g_best[BB][TP][NTILES];// per-tile argmax keys

// ---------------------------------------------------------------------------
// K0: zero output + spike counters
__global__ void k_zero(float4* __restrict__ out4, int n4) {
    int i = blockIdx.x * blockDim.x + threadIdx.x;
    int stride = gridDim.x * blockDim.x;
    float4 z = make_float4(0.f, 0.f, 0.f, 0.f);
    for (int j = i; j < n4; j += stride) out4[j] = z;
    int* cnt = &g_cnt[0][0];
    for (int j = i; j < BB * TT; j += stride) cnt[j] = 0;
}

// ---------------------------------------------------------------------------
// K1: build per-(b,t) active-synapse lists.  grid (SS, BB), 512 threads over t.
__global__ void k_spikes(const float* __restrict__ x) {
    int s = blockIdx.x, b = blockIdx.y;
    int t = threadIdx.x;
    if (t < TT) {
        float v = x[((size_t)b * SS + s) * TT + t];
        if (v > 0.5f) {
            int p = atomicAdd(&g_cnt[b][t], 1);
            g_spk[b][t][p] = (unsigned short)s;
        }
    }
}

// ---------------------------------------------------------------------------
// K2: potentials + per-tile argmax.  grid = BB*NTILES, block = 512.
// smem: sw[784*32] bytes (=4*weight, [s][n]), scnt2[SLOTS][32] u64 counts,
//       wl[16][128] u16 per-warp spike staging, cc[21] u64 packed dp4a coeffs.
#define SW_BYTES   (SS * NTILE)                  // 25088
#define SCNT_BYTES (SLOTS * NTILE * 8)           // 27648
#define WL_BYTES   (NWARPS * 128 * 2)            // 4096
#define CC_BYTES   (KS * 8)                      // 168
#define SMEM_BYTES (SW_BYTES + SCNT_BYTES + WL_BYTES + CC_BYTES)

#define NMASK 0x0F0F0F0Fu

__global__ __launch_bounds__(512, 2) void k_pot(const int* __restrict__ weight,
                                                const int* __restrict__ table) {
    extern __shared__ unsigned char smem[];
    unsigned char* sw = smem;
    unsigned long long* scnt2 = (unsigned long long*)(smem + SW_BYTES);
    unsigned short* wl = (unsigned short*)(smem + SW_BYTES + SCNT_BYTES);
    unsigned long long* cc = (unsigned long long*)(smem + SW_BYTES + SCNT_BYTES + WL_BYTES);

    int b = blockIdx.x >> 4, tile = blockIdx.x & 15;
    int tid = threadIdx.x, lane = tid & 31, warp = tid >> 5;

    // packed coefficients: cc[d] = (cO[d]<<32)|cE[d], where
    // cE[d] = bytes {table[0][20-d], table[2][20-d], table[4][20-d], table[6][20-d]}
    if (tid < KS) {
        unsigned e = 0, o = 0;
#pragma unroll
        for (int w = 0; w < 4; w++) {
            e |= (unsigned)table[(2 * w) * KS + (KS - 1 - tid)] << (8 * w);
            o |= (unsigned)table[(2 * w + 1) * KS + (KS - 1 - tid)] << (8 * w);
        }
        cc[tid] = (unsigned long long)e | ((unsigned long long)o << 32);
    }
    // weights -> smem as shift amounts (4*w), layout [s][n]
    for (int idx = tid; idx < NTILE * SS; idx += 512) {
        int n = idx / SS, s = idx - n * SS;
        sw[(s << 5) + n] = (unsigned char)(weight[(size_t)(tile * NTILE + n) * SS + s] << 2);
    }

    unsigned short* wlw = wl + warp * 128;

    for (int chunk = 0; chunk < TP / CH; chunk++) {
        int c0 = chunk * CH;
        __syncthreads();   // prev Phase B done reading scnt2

        // halo: slots [0,20] = prev slots [CH, CH+20], or zero for chunk 0
        for (int idx = tid; idx < KS * NTILE; idx += 512) {
            scnt2[idx] = chunk ? scnt2[CH * NTILE + idx] : 0ull;
        }
        __syncthreads();

        // ---- Phase A: histograms for t in [c0, c0+CH) ----
        for (int i = 0; i < (CH + NWARPS - 1) / NWARPS; i++) {
            int t = c0 + warp + i * NWARPS;
            if (t >= c0 + CH) break;
            int slot = t - c0 + KS;
            unsigned long long* dst = &scnt2[slot << 5];
            if (t >= TT) { dst[lane] = 0ull; continue; }

            int cnt = g_cnt[b][t];
            const unsigned short* lst = g_spk[b][t];
            unsigned accE = 0, accO = 0;

            for (int j0 = 0; j0 < cnt; j0 += 128) {
                int m = min(128, cnt - j0);
                // cooperative coalesced staging (u32 granules; row is u32-aligned)
                int nw = (m + 1) >> 1;
                for (int k = lane; k < nw; k += 32)
                    ((unsigned*)wlw)[k] = ((const unsigned*)(lst + j0))[k];
                __syncwarp();

                int k = 0;
                for (; k + 8 <= m; k += 8) {
                    int s0 = wlw[k + 0], s1 = wlw[k + 1], s2 = wlw[k + 2], s3 = wlw[k + 3];
                    int s4 = wlw[k + 4], s5 = wlw[k + 5], s6 = wlw[k + 6], s7 = wlw[k + 7];
                    unsigned nA = (1u << sw[(s0 << 5) + lane]) + (1u << sw[(s2 << 5) + lane])
                                + (1u << sw[(s4 << 5) + lane]) + (1u << sw[(s6 << 5) + lane]);
                    unsigned nB = (1u << sw[(s1 << 5) + lane]) + (1u << sw[(s3 << 5) + lane])
                                + (1u << sw[(s5 << 5) + lane]) + (1u << sw[(s7 << 5) + lane]);
                    accE += (nA & NMASK) + (nB & NMASK);
                    accO += ((nA >> 4) & NMASK) + ((nB >> 4) & NMASK);
                }
                unsigned nib = 0;
                for (; k < m; k++) nib += 1u << sw[((int)wlw[k] << 5) + lane];
                accE += nib & NMASK;
                accO += (nib >> 4) & NMASK;
                __syncwarp();
            }
            dst[lane] = (unsigned long long)accE | ((unsigned long long)accO << 32);
        }
        __syncthreads();

        // ---- Phase B: 21-tap dp4a conv + warp argmax ----
        for (int j = warp; j < CH; j += NWARPS) {
            int tau = c0 + j;           // always < 522
            unsigned pot = 0;
#pragma unroll
            for (int d = 0; d < KS; d++) {
                unsigned long long v = scnt2[((j + 20 - d) << 5) + lane];
                unsigned long long c = cc[d];
                pot = __dp4a((unsigned)v, (unsigned)c, pot);
                pot = __dp4a((unsigned)(v >> 32), (unsigned)(c >> 32), pot);
            }
            // key embeds global tie-break: first index wins on equal pot
            unsigned key = (pot << 12) | ((unsigned)(15 - tile) << 8) | (255u - lane);
            unsigned best = __reduce_max_sync(0xffffffffu, key);
            if (lane == 0) g_best[b][tau][tile] = (int)best;
        }
    }
}

// ---------------------------------------------------------------------------
// K3: reduce tiles + sequential depression scan. grid = BB, block = 256.
__global__ void k_scan(float* __restrict__ out) {
    int b = blockIdx.x, tid = threadIdx.x;
    __shared__ int mk[TP];   // packed (pot<<10)|neuron
    for (int tau = tid; tau < TP; tau += blockDim.x) {
        const int4* p = (const int4*)&g_best[b][tau][0];
        int4 a = p[0], c = p[1], d = p[2], e = p[3];
        int m = max(max(max(a.x, a.y), max(a.z, a.w)),
                    max(max(max(c.x, c.y), max(c.z, c.w)),
                        max(max(max(d.x, d.y), max(d.z, d.w)),
                            max(max(e.x, e.y), max(e.z, e.w)))));
        int pot = (int)((unsigned)m >> 12);
        int neuron = (15 - ((m >> 8) & 15)) * 32 + (255 - (m & 255));
        mk[tau] = (pot << 10) | neuron;
    }
    __syncthreads();
    if (tid == 0) {
        int dep = 0;
        for (int tau = 0; tau < TP; tau++) {
            int v = mk[tau];
            if ((v >> 10) > THETA && dep == 0) {
                out[((size_t)b * NN + (v & 1023)) * TP + tau] = 1.0f;
                dep = 22;     // becomes 21 after decrement, matching reference
            }
            dep = max(0, dep - 1);
        }
    }
}

// ---------------------------------------------------------------------------
extern "C" void kernel_launch(void* const* d_in, const int* in_sizes, int n_in,
                              void* d_out, int out_size) {
    const float* x      = (const float*)d_in[0];
    const int*   weight = (const int*)d_in[1];
    const int*   table  = (const int*)d_in[2];
    float* out = (float*)d_out;

    cudaFuncSetAttribute(k_pot, cudaFuncAttributeMaxDynamicSharedMemorySize, SMEM_BYTES);

    int n4 = out_size / 4;
    k_zero<<<2048, 256>>>((float4*)out, n4);
    k_spikes<<<dim3(SS, BB), 512>>>(x);
    k_pot<<<BB * NTILES, 512, SMEM_BYTES>>>(weight, table);
    k_scan<<<BB, 256>>>(out);
}